// round 3
// baseline (speedup 1.0000x reference)
#include <cuda_runtime.h>
#include <math.h>
#include <stdint.h>

#define B_  128
#define T_  1024
#define NX_ 256
#define NH_ 512
#define NY_ 256

// ---------------------------------------------------------------------------
// Generic NT SGEMM: C[m][n] = sum_k A[m][k] * B[n][k]
// ---------------------------------------------------------------------------
template <int BM, int BN, int BK, int TM, int TN, int NT>
__global__ __launch_bounds__(NT) void sgemm_nt(
    const float* __restrict__ A,
    const float* __restrict__ Bm,
    float* __restrict__ C,
    int M, int N, int K)
{
    __shared__ float As[BK][BM];
    __shared__ float Bs[BK][BN];

    const int tid = threadIdx.x;
    const int m0 = blockIdx.y * BM;
    const int n0 = blockIdx.x * BN;
    const int tx = tid % (BN / TN);
    const int ty = tid / (BN / TN);

    float acc[TM][TN];
#pragma unroll
    for (int i = 0; i < TM; i++)
#pragma unroll
        for (int j = 0; j < TN; j++) acc[i][j] = 0.0f;

    for (int k0 = 0; k0 < K; k0 += BK) {
#pragma unroll
        for (int i = tid; i < BM * (BK / 4); i += NT) {
            int m = i / (BK / 4);
            int kq = (i % (BK / 4)) * 4;
            float4 v = *(const float4*)(A + (long)(m0 + m) * K + k0 + kq);
            As[kq + 0][m] = v.x;
            As[kq + 1][m] = v.y;
            As[kq + 2][m] = v.z;
            As[kq + 3][m] = v.w;
        }
#pragma unroll
        for (int i = tid; i < BN * (BK / 4); i += NT) {
            int n = i / (BK / 4);
            int kq = (i % (BK / 4)) * 4;
            float4 v = *(const float4*)(Bm + (long)(n0 + n) * K + k0 + kq);
            Bs[kq + 0][n] = v.x;
            Bs[kq + 1][n] = v.y;
            Bs[kq + 2][n] = v.z;
            Bs[kq + 3][n] = v.w;
        }
        __syncthreads();

#pragma unroll
        for (int k = 0; k < BK; ++k) {
            float a[TM], b[TN];
#pragma unroll
            for (int i = 0; i < TM; i++) a[i] = As[k][ty * TM + i];
#pragma unroll
            for (int j = 0; j < TN; j++) b[j] = Bs[k][tx * TN + j];
#pragma unroll
            for (int i = 0; i < TM; i++)
#pragma unroll
                for (int j = 0; j < TN; j++) acc[i][j] = fmaf(a[i], b[j], acc[i][j]);
        }
        __syncthreads();
    }

#pragma unroll
    for (int i = 0; i < TM; i++) {
        float4 v = make_float4(acc[i][0], acc[i][1], acc[i][2], acc[i][3]);
        *(float4*)(C + (long)(m0 + ty * TM + i) * N + n0 + tx * TN) = v;
    }
}

// ---------------------------------------------------------------------------
// Sequential recurrence: cluster-of-8 version.
// Grid = 128 CTAs = 16 clusters x 8. Cluster handles 8 batches; rank jt owns
// 64 output columns. h lives in SMEM (double-buffered, full K=512 for the 8
// batches, replicated per CTA). Each CTA pushes its 8x64 h-slice into all 8
// cluster CTAs' hT[next] via DSMEM, then one barrier.cluster per step.
// ---------------------------------------------------------------------------
#define CL   8
#define BB   8
#define JT   64
#define NTHR 512

#define WHT_OFF 0                        // whT[k][jloc]: 512 x 64
#define HT_OFF  (NH_ * JT)               // hT[2][k][b]:  2 x 512 x 8
#define RED_OFF (HT_OFF + 2 * NH_ * BB)  // red[w][jl*9+b]: 16 x 576
#define SMEM_FLOATS (RED_OFF + 16 * 576)
#define SMEM_BYTES  (SMEM_FLOATS * 4)    // 200704

__device__ __forceinline__ void st_dsmem_f32(uint32_t addr, uint32_t rank, float v)
{
    asm volatile(
        "{\n\t"
        ".reg .b32 r;\n\t"
        "mapa.shared::cluster.u32 r, %0, %1;\n\t"
        "st.shared::cluster.f32 [r], %2;\n\t"
        "}"
        :: "r"(addr), "r"(rank), "f"(v) : "memory");
}

__global__ __launch_bounds__(NTHR, 1) __cluster_dims__(CL, 1, 1)
void rnn_seq_cl(const float* __restrict__ Wh,
                const float* __restrict__ h0,
                float* __restrict__ hs)
{
    extern __shared__ float sm[];
    float* whT = sm + WHT_OFF;
    float* hT  = sm + HT_OFF;
    float* red = sm + RED_OFF;

    const int tid  = threadIdx.x;
    const int wid  = tid >> 5;
    const int lane = tid & 31;

    const int jt  = blockIdx.x & (CL - 1);
    const int bt  = blockIdx.x / CL;
    const int b0g = bt * BB;
    const int j0g = jt * JT;

    uint32_t smem_base;
    asm("{ .reg .u64 t; cvta.to.shared.u64 t, %1; cvt.u32.u64 %0, t; }"
        : "=r"(smem_base) : "l"(sm));

    for (int i = tid; i < JT * (NH_ / 4); i += NTHR) {
        int jl = i / (NH_ / 4);
        int k4 = (i % (NH_ / 4)) * 4;
        float4 v = *(const float4*)(Wh + (size_t)(j0g + jl) * NH_ + k4);
        whT[(k4 + 0) * JT + jl] = v.x;
        whT[(k4 + 1) * JT + jl] = v.y;
        whT[(k4 + 2) * JT + jl] = v.z;
        whT[(k4 + 3) * JT + jl] = v.w;
    }
    for (int i = tid; i < NH_ * BB; i += NTHR) {
        int k = i >> 3, b = i & 7;
        hT[i] = h0[(size_t)(b0g + b) * NH_ + k];
    }
    __syncthreads();

    const int bg2 = (lane >> 3) * 2;
    const int jg8 = (lane & 7) * 8;
    const int kw0 = wid * 32;

    const int ejl = tid >> 3;
    const int eb  = tid & 7;

    for (int t = 0; t < T_; ++t) {
        const float* htc = hT + (t & 1) * (NH_ * BB);

        const float* prep = hs + ((size_t)(b0g + eb) * T_ + t) * NH_ + j0g + ejl;
        float pre = __ldcg(prep);

        float acc[2][8];
#pragma unroll
        for (int i = 0; i < 2; i++)
#pragma unroll
            for (int j = 0; j < 8; j++) acc[i][j] = 0.0f;

#pragma unroll 8
        for (int k = kw0; k < kw0 + 32; ++k) {
            float2 a  = *(const float2*)(htc + k * 8 + bg2);
            float4 w0 = *(const float4*)(whT + k * JT + jg8);
            float4 w1 = *(const float4*)(whT + k * JT + jg8 + 4);
            acc[0][0] = fmaf(a.x, w0.x, acc[0][0]);
            acc[0][1] = fmaf(a.x, w0.y, acc[0][1]);
            acc[0][2] = fmaf(a.x, w0.z, acc[0][2]);
            acc[0][3] = fmaf(a.x, w0.w, acc[0][3]);
            acc[0][4] = fmaf(a.x, w1.x, acc[0][4]);
            acc[0][5] = fmaf(a.x, w1.y, acc[0][5]);
            acc[0][6] = fmaf(a.x, w1.z, acc[0][6]);
            acc[0][7] = fmaf(a.x, w1.w, acc[0][7]);
            acc[1][0] = fmaf(a.y, w0.x, acc[1][0]);
            acc[1][1] = fmaf(a.y, w0.y, acc[1][1]);
            acc[1][2] = fmaf(a.y, w0.z, acc[1][2]);
            acc[1][3] = fmaf(a.y, w0.w, acc[1][3]);
            acc[1][4] = fmaf(a.y, w1.x, acc[1][4]);
            acc[1][5] = fmaf(a.y, w1.y, acc[1][5]);
            acc[1][6] = fmaf(a.y, w1.z, acc[1][6]);
            acc[1][7] = fmaf(a.y, w1.w, acc[1][7]);
        }

#pragma unroll
        for (int i = 0; i < 2; i++)
#pragma unroll
            for (int j = 0; j < 8; j++)
                red[wid * 576 + (jg8 + j) * 9 + (bg2 + i)] = acc[i][j];
        __syncthreads();

        float s = pre;
#pragma unroll
        for (int w = 0; w < 16; w++) s += red[w * 576 + ejl * 9 + eb];
        float hv = tanhf(s);

        hs[((size_t)(b0g + eb) * T_ + t) * NH_ + j0g + ejl] = hv;

        const int nxt = (t + 1) & 1;
        uint32_t dst = smem_base +
            (uint32_t)(HT_OFF + nxt * (NH_ * BB) + (j0g + ejl) * 8 + eb) * 4u;
#pragma unroll
        for (int r = 0; r < CL; r++) st_dsmem_f32(dst, r, hv);

        asm volatile("barrier.cluster.arrive.aligned;" ::: "memory");
        asm volatile("barrier.cluster.wait.aligned;" ::: "memory");
    }
}

// ---------------------------------------------------------------------------
// Launch
// ---------------------------------------------------------------------------
extern "C" void kernel_launch(void* const* d_in, const int* in_sizes, int n_in,
                              void* d_out, int out_size)
{
    const float* x  = (const float*)d_in[0];
    const float* h0 = (const float*)d_in[1];
    const float* Wi = (const float*)d_in[2];
    const float* Wh = (const float*)d_in[3];
    const float* Wy = (const float*)d_in[4];

    float* y  = (float*)d_out;
    float* hs = y + (size_t)B_ * T_ * NY_;

    // Phase 1: pre = x @ Wi^T  -> hs region (scratch)
    {
        dim3 grid(NH_ / 64, (B_ * T_) / 128);
        sgemm_nt<128, 64, 16, 8, 4, 256><<<grid, 256>>>(x, Wi, hs, B_ * T_, NH_, NX_);
    }
    // Phase 2: sequential recurrence (16 independent clusters of 8)
    {
        cudaFuncSetAttribute(rnn_seq_cl,
                             cudaFuncAttributeMaxDynamicSharedMemorySize, SMEM_BYTES);
        rnn_seq_cl<<<128, NTHR, SMEM_BYTES>>>(Wh, h0, hs);
    }
    // Phase 3: y = hs @ Wy^T
    {
        dim3 grid(NY_ / 64, (B_ * T_) / 128);
        sgemm_nt<128, 64, 16, 8, 4, 256><<<grid, 256>>>(hs, Wy, y, B_ * T_, NY_, NH_);
    }
}

// round 4
// speedup vs baseline: 1.1106x; 1.1106x over previous
#include <cuda_runtime.h>
#include <math.h>
#include <stdint.h>

#define B_  128
#define T_  1024
#define NX_ 256
#define NH_ 512
#define NY_ 256

// ---------------------------------------------------------------------------
// Generic NT SGEMM: C[m][n] = sum_k A[m][k] * B[n][k]   (unchanged from R1)
// ---------------------------------------------------------------------------
template <int BM, int BN, int BK, int TM, int TN, int NT>
__global__ __launch_bounds__(NT) void sgemm_nt(
    const float* __restrict__ A,
    const float* __restrict__ Bm,
    float* __restrict__ C,
    int M, int N, int K)
{
    __shared__ float As[BK][BM];
    __shared__ float Bs[BK][BN];

    const int tid = threadIdx.x;
    const int m0 = blockIdx.y * BM;
    const int n0 = blockIdx.x * BN;
    const int tx = tid % (BN / TN);
    const int ty = tid / (BN / TN);

    float acc[TM][TN];
#pragma unroll
    for (int i = 0; i < TM; i++)
#pragma unroll
        for (int j = 0; j < TN; j++) acc[i][j] = 0.0f;

    for (int k0 = 0; k0 < K; k0 += BK) {
#pragma unroll
        for (int i = tid; i < BM * (BK / 4); i += NT) {
            int m = i / (BK / 4);
            int kq = (i % (BK / 4)) * 4;
            float4 v = *(const float4*)(A + (long)(m0 + m) * K + k0 + kq);
            As[kq + 0][m] = v.x;
            As[kq + 1][m] = v.y;
            As[kq + 2][m] = v.z;
            As[kq + 3][m] = v.w;
        }
#pragma unroll
        for (int i = tid; i < BN * (BK / 4); i += NT) {
            int n = i / (BK / 4);
            int kq = (i % (BK / 4)) * 4;
            float4 v = *(const float4*)(Bm + (long)(n0 + n) * K + k0 + kq);
            Bs[kq + 0][n] = v.x;
            Bs[kq + 1][n] = v.y;
            Bs[kq + 2][n] = v.z;
            Bs[kq + 3][n] = v.w;
        }
        __syncthreads();

#pragma unroll
        for (int k = 0; k < BK; ++k) {
            float a[TM], b[TN];
#pragma unroll
            for (int i = 0; i < TM; i++) a[i] = As[k][ty * TM + i];
#pragma unroll
            for (int j = 0; j < TN; j++) b[j] = Bs[k][tx * TN + j];
#pragma unroll
            for (int i = 0; i < TM; i++)
#pragma unroll
                for (int j = 0; j < TN; j++) acc[i][j] = fmaf(a[i], b[j], acc[i][j]);
        }
        __syncthreads();
    }

#pragma unroll
    for (int i = 0; i < TM; i++) {
        float4 v = make_float4(acc[i][0], acc[i][1], acc[i][2], acc[i][3]);
        *(float4*)(C + (long)(m0 + ty * TM + i) * N + n0 + tx * TN) = v;
    }
}

// ---------------------------------------------------------------------------
// Sequential recurrence: cluster-of-8, mbarrier-pipelined DSMEM bulk exchange.
//
// 16 clusters x 8 CTAs. Cluster -> 8 batches; rank jt -> 64 output columns.
// h double-buffered in SMEM as hT[s][k][b]. Per step each CTA:
//   wait full[s] (tx-counted mbarrier, acquire.cluster)
//   FFMA2 loop over full k=512 (16 warps k-split), SMEM reduce, tanh
//   write own 2KB chunk into local hT[s^1], then 7x cp.async.bulk (S2S,
//   cluster) to peers, each signaling the destination's full[s^1] barrier.
// No cluster barrier in the loop; skew is absorbed by mbarrier waits.
// ---------------------------------------------------------------------------
#define CL   8
#define BB   8
#define JT   64
#define NTHR 512

#define HSZ       (NH_ * BB)                 // 4096 floats per h buffer
#define WHT_OFF   0                          // whT[k][jloc]: 512 x 64
#define HT_OFF    (NH_ * JT)                 // 32768
#define RED_OFF   (HT_OFF + 2 * HSZ)         // 40960 : red[w][j*9+b], 16 x 576
#define MBAR_OFF  (RED_OFF + 16 * 576)       // 50176 floats
#define SMEM_FLOATS (MBAR_OFF + 8)
#define SMEM_BYTES  (SMEM_FLOATS * 4)        // 200736

#define CHUNK_BYTES   (JT * BB * 4)          // 2048
#define EXPECT_BYTES  ((CL - 1) * CHUNK_BYTES) // 14336

// ---- small PTX helpers ----
__device__ __forceinline__ uint32_t smem_u32(const void* p)
{
    uint32_t a;
    asm("{ .reg .u64 t; cvta.to.shared.u64 t, %1; cvt.u32.u64 %0, t; }"
        : "=r"(a) : "l"(p));
    return a;
}
__device__ __forceinline__ uint32_t mapa_rank(uint32_t addr, uint32_t rank)
{
    uint32_t r;
    asm("mapa.shared::cluster.u32 %0, %1, %2;" : "=r"(r) : "r"(addr), "r"(rank));
    return r;
}
__device__ __forceinline__ unsigned long long pack2(float x)
{
    unsigned long long r;
    asm("mov.b64 %0, {%1, %1};" : "=l"(r) : "f"(x));
    return r;
}
__device__ __forceinline__ void unpack2(unsigned long long v, float& lo, float& hi)
{
    asm("mov.b64 {%0, %1}, %2;" : "=f"(lo), "=f"(hi) : "l"(v));
}
__device__ __forceinline__ void ffma2(unsigned long long& d,
                                      unsigned long long a, unsigned long long b)
{
    asm("fma.rn.f32x2 %0, %1, %2, %0;" : "+l"(d) : "l"(a), "l"(b));
}

#define MBAR_INIT(a, n) \
    asm volatile("mbarrier.init.shared.b64 [%0], %1;" :: "r"(a), "r"(n) : "memory")
#define MBAR_EXPECT_TX(a, bytes) \
    asm volatile("mbarrier.arrive.expect_tx.shared.b64 _, [%0], %1;" \
                 :: "r"(a), "r"(bytes) : "memory")

#define MBAR_WAIT_PARITY_CL(mbar, parity) do {                                  \
    asm volatile(                                                               \
        "{\n\t"                                                                 \
        ".reg .pred P1;\n\t"                                                    \
        "WL_%=:\n\t"                                                            \
        "mbarrier.try_wait.parity.acquire.cluster.shared::cta.b64 P1, [%0], %1, 0x989680;\n\t" \
        "@P1 bra.uni WD_%=;\n\t"                                                \
        "bra.uni WL_%=;\n\t"                                                    \
        "WD_%=:\n\t"                                                            \
        "}"                                                                     \
        :: "r"(mbar), "r"(parity) : "memory");                                  \
} while (0)

__global__ __launch_bounds__(NTHR, 1) __cluster_dims__(CL, 1, 1)
void rnn_seq_mb(const float* __restrict__ Wh,
                const float* __restrict__ h0,
                float* __restrict__ hs)
{
    extern __shared__ float sm[];
    float* whT = sm + WHT_OFF;
    float* hT  = sm + HT_OFF;
    float* red = sm + RED_OFF;

    const int tid  = threadIdx.x;
    const int wid  = tid >> 5;
    const int lane = tid & 31;

    const int jt  = blockIdx.x & (CL - 1);
    const int bt  = blockIdx.x / CL;
    const int b0g = bt * BB;
    const int j0g = jt * JT;

    const uint32_t smem_base = smem_u32(sm);
    const uint32_t mbar0 = smem_base + MBAR_OFF * 4;     // full[0]
    const uint32_t mbar1 = mbar0 + 8;                    // full[1]

    // Resident Wh tile, transposed: whT[k][jloc]
    for (int i = tid; i < JT * (NH_ / 4); i += NTHR) {
        int jl = i / (NH_ / 4);
        int k4 = (i % (NH_ / 4)) * 4;
        float4 v = *(const float4*)(Wh + (size_t)(j0g + jl) * NH_ + k4);
        whT[(k4 + 0) * JT + jl] = v.x;
        whT[(k4 + 1) * JT + jl] = v.y;
        whT[(k4 + 2) * JT + jl] = v.z;
        whT[(k4 + 3) * JT + jl] = v.w;
    }
    // Preload buffer 0 with h0: hT[0][k][b]
    for (int i = tid; i < HSZ; i += NTHR) {
        int k = i >> 3, b = i & 7;
        hT[i] = h0[(size_t)(b0g + b) * NH_ + k];
    }
    if (tid == 0) {
        MBAR_INIT(mbar0, 1);
        MBAR_INIT(mbar1, 1);
        MBAR_EXPECT_TX(mbar1, EXPECT_BYTES);   // for step t=1
        MBAR_EXPECT_TX(mbar0, EXPECT_BYTES);   // for step t=2
    }
    __syncthreads();
    // Barrier inits must be cluster-visible before any peer's copy arrives.
    asm volatile("barrier.cluster.arrive.aligned;" ::: "memory");
    asm volatile("barrier.cluster.wait.aligned;" ::: "memory");

    // Compute mapping: 16 warps k-split (32 each); thread tile 2b x 8j (FFMA2 over j-pairs)
    const int bg2 = (lane >> 3) * 2;
    const int jg8 = (lane & 7) * 8;
    const int kw0 = wid * 32;

    // Epilogue mapping: one element per thread
    const int ejl = tid >> 3;    // 0..63 local j
    const int eb  = tid & 7;     // 0..7  local b

    int ph0 = 0, ph1 = 0;

    for (int t = 0; t < T_; ++t) {
        const int s  = t & 1;
        const int s2 = s ^ 1;
        const float* htc = hT + s * HSZ;

        // Prefetch pre-activation (independent of the barrier)
        float pre = __ldcg(hs + ((size_t)(b0g + eb) * T_ + t) * NH_ + j0g + ejl);

        if (t > 0) {
            const uint32_t mb = s ? mbar1 : mbar0;
            const int      ph = s ? ph1 : ph0;
            MBAR_WAIT_PARITY_CL(mb, ph);
            if (s) ph1 ^= 1; else ph0 ^= 1;
            if (tid == 0 && t + 2 < T_) MBAR_EXPECT_TX(mb, EXPECT_BYTES);
        }

        unsigned long long acc[2][4];
#pragma unroll
        for (int i = 0; i < 2; i++)
#pragma unroll
            for (int p = 0; p < 4; p++) acc[i][p] = 0ull;

#pragma unroll 8
        for (int k = kw0; k < kw0 + 32; ++k) {
            float2 a = *(const float2*)(htc + k * 8 + bg2);
            unsigned long long ax = pack2(a.x);
            unsigned long long ay = pack2(a.y);
            ulonglong2 W0 = *(const ulonglong2*)(whT + k * JT + jg8);
            ulonglong2 W1 = *(const ulonglong2*)(whT + k * JT + jg8 + 4);
            ffma2(acc[0][0], ax, W0.x);
            ffma2(acc[0][1], ax, W0.y);
            ffma2(acc[0][2], ax, W1.x);
            ffma2(acc[0][3], ax, W1.y);
            ffma2(acc[1][0], ay, W0.x);
            ffma2(acc[1][1], ay, W0.y);
            ffma2(acc[1][2], ay, W1.x);
            ffma2(acc[1][3], ay, W1.y);
        }

        // Stash partials (scalar, same proven layout as R3)
#pragma unroll
        for (int i = 0; i < 2; i++)
#pragma unroll
            for (int p = 0; p < 4; p++) {
                float lo, hi;
                unpack2(acc[i][p], lo, hi);
                red[wid * 576 + (jg8 + 2 * p) * 9     + (bg2 + i)] = lo;
                red[wid * 576 + (jg8 + 2 * p + 1) * 9 + (bg2 + i)] = hi;
            }
        __syncthreads();

        // Reduce 16 warps + pre, tanh
        float sacc = pre;
#pragma unroll
        for (int w = 0; w < 16; w++) sacc += red[w * 576 + ejl * 9 + eb];
        float hv = tanhf(sacc);

        // Output + local write of own chunk into hT[s2]
        hs[((size_t)(b0g + eb) * T_ + t) * NH_ + j0g + ejl] = hv;
        hT[s2 * HSZ + (j0g + ejl) * BB + eb] = hv;
        __syncthreads();

        // Push own 2KB chunk to the 7 peers; each copy signals the
        // destination's full[s2] barrier via complete_tx.
        if (t < T_ - 1 && tid < CL && tid != jt) {
            asm volatile("fence.proxy.async.shared::cta;" ::: "memory");
            uint32_t src = smem_base + (uint32_t)(HT_OFF + s2 * HSZ + j0g * BB) * 4u;
            uint32_t dst = mapa_rank(src, (uint32_t)tid);
            uint32_t mb  = mapa_rank(s2 ? mbar1 : mbar0, (uint32_t)tid);
            asm volatile(
                "cp.async.bulk.shared::cluster.shared::cta.mbarrier::complete_tx::bytes "
                "[%0], [%1], %2, [%3];"
                :: "r"(dst), "r"(src), "r"(CHUNK_BYTES), "r"(mb) : "memory");
        }
    }

    // No CTA may exit while peers could still target its SMEM.
    asm volatile("barrier.cluster.arrive.aligned;" ::: "memory");
    asm volatile("barrier.cluster.wait.aligned;" ::: "memory");
}

// ---------------------------------------------------------------------------
// Launch
// ---------------------------------------------------------------------------
extern "C" void kernel_launch(void* const* d_in, const int* in_sizes, int n_in,
                              void* d_out, int out_size)
{
    const float* x  = (const float*)d_in[0];
    const float* h0 = (const float*)d_in[1];
    const float* Wi = (const float*)d_in[2];
    const float* Wh = (const float*)d_in[3];
    const float* Wy = (const float*)d_in[4];

    float* y  = (float*)d_out;
    float* hs = y + (size_t)B_ * T_ * NY_;

    // Phase 1: pre = x @ Wi^T  -> hs region (scratch)
    {
        dim3 grid(NH_ / 64, (B_ * T_) / 128);
        sgemm_nt<128, 64, 16, 8, 4, 256><<<grid, 256>>>(x, Wi, hs, B_ * T_, NH_, NX_);
    }
    // Phase 2: sequential recurrence
    {
        cudaFuncSetAttribute(rnn_seq_mb,
                             cudaFuncAttributeMaxDynamicSharedMemorySize, SMEM_BYTES);
        rnn_seq_mb<<<128, NTHR, SMEM_BYTES>>>(Wh, h0, hs);
    }
    // Phase 3: y = hs @ Wy^T
    {
        dim3 grid(NY_ / 64, (B_ * T_) / 128);
        sgemm_nt<128, 64, 16, 8, 4, 256><<<grid, 256>>>(hs, Wy, y, B_ * T_, NY_, NH_);
    }
}